// round 1
// baseline (speedup 1.0000x reference)
#include <cuda_runtime.h>
#include <math.h>

// Problem: x[1, 2_000_000, 16] fp32, ~5% NaN. Per column c: mean over valid
// entries along T; output = x with NaNs replaced by column mean.
//
// 3 launches: zero accumulators -> column reduction -> fill.

#define C 16
#define CG 4              // columns per float4
#define THREADS 256
#define RBLOCKS 2048      // reduction grid
#define FBLOCKS 2048      // fill grid

__device__ float g_sum[C];
__device__ float g_cnt[C];

__global__ void zero_kernel() {
    int t = threadIdx.x;
    if (t < C) { g_sum[t] = 0.0f; g_cnt[t] = 0.0f; }
}

__global__ void reduce_kernel(const float4* __restrict__ in, long long n4) {
    __shared__ float s_sum[C];
    __shared__ float s_cnt[C];
    if (threadIdx.x < C) { s_sum[threadIdx.x] = 0.0f; s_cnt[threadIdx.x] = 0.0f; }
    __syncthreads();

    long long tid    = (long long)blockIdx.x * blockDim.x + threadIdx.x;
    long long stride = (long long)gridDim.x * blockDim.x;   // multiple of 4
    int cg = (int)(tid & 3);                                // fixed column group

    float lsum0 = 0.f, lsum1 = 0.f, lsum2 = 0.f, lsum3 = 0.f;
    float lcnt0 = 0.f, lcnt1 = 0.f, lcnt2 = 0.f, lcnt3 = 0.f;

    for (long long i = tid; i < n4; i += stride) {
        float4 v = in[i];
        bool v0 = (v.x == v.x);
        bool v1 = (v.y == v.y);
        bool v2 = (v.z == v.z);
        bool v3 = (v.w == v.w);
        if (v0) { lsum0 += v.x; lcnt0 += 1.f; }
        if (v1) { lsum1 += v.y; lcnt1 += 1.f; }
        if (v2) { lsum2 += v.z; lcnt2 += 1.f; }
        if (v3) { lsum3 += v.w; lcnt3 += 1.f; }
    }

    int base = cg * 4;
    atomicAdd(&s_sum[base + 0], lsum0);
    atomicAdd(&s_sum[base + 1], lsum1);
    atomicAdd(&s_sum[base + 2], lsum2);
    atomicAdd(&s_sum[base + 3], lsum3);
    atomicAdd(&s_cnt[base + 0], lcnt0);
    atomicAdd(&s_cnt[base + 1], lcnt1);
    atomicAdd(&s_cnt[base + 2], lcnt2);
    atomicAdd(&s_cnt[base + 3], lcnt3);
    __syncthreads();

    if (threadIdx.x < C) {
        atomicAdd(&g_sum[threadIdx.x], s_sum[threadIdx.x]);
        atomicAdd(&g_cnt[threadIdx.x], s_cnt[threadIdx.x]);
    }
}

__global__ void fill_kernel(const float4* __restrict__ in,
                            float4* __restrict__ out, long long n4) {
    long long tid    = (long long)blockIdx.x * blockDim.x + threadIdx.x;
    long long stride = (long long)gridDim.x * blockDim.x;   // multiple of 4
    int cg = (int)(tid & 3);
    int base = cg * 4;

    float m0 = g_sum[base + 0] / fmaxf(g_cnt[base + 0], 1.0f);
    float m1 = g_sum[base + 1] / fmaxf(g_cnt[base + 1], 1.0f);
    float m2 = g_sum[base + 2] / fmaxf(g_cnt[base + 2], 1.0f);
    float m3 = g_sum[base + 3] / fmaxf(g_cnt[base + 3], 1.0f);

    for (long long i = tid; i < n4; i += stride) {
        float4 v = in[i];
        if (!(v.x == v.x)) v.x = m0;
        if (!(v.y == v.y)) v.y = m1;
        if (!(v.z == v.z)) v.z = m2;
        if (!(v.w == v.w)) v.w = m3;
        out[i] = v;
    }
}

extern "C" void kernel_launch(void* const* d_in, const int* in_sizes, int n_in,
                              void* d_out, int out_size) {
    const float* in = (const float*)d_in[0];
    float* out = (float*)d_out;
    long long n  = (long long)in_sizes[0];   // 32M floats
    long long n4 = n / 4;

    zero_kernel<<<1, 32>>>();
    reduce_kernel<<<RBLOCKS, THREADS>>>((const float4*)in, n4);
    fill_kernel<<<FBLOCKS, THREADS>>>((const float4*)in, (float4*)out, n4);
}

// round 3
// speedup vs baseline: 1.3063x; 1.3063x over previous
#include <cuda_runtime.h>
#include <math.h>

// x[1, 2M, 16] fp32, ~5% NaN. Per-column mean of valid entries; NaNs -> mean.
// Single fused persistent kernel with software grid barrier:
//   phase1: per-block contiguous-tile reduction -> global atomics
//   grid barrier (threadfence-reduction pattern)
//   phase2: reverse-order re-read of own tile (L2 hot) + NaN fill + write
// Accumulators + barrier counter zeroed by one cudaMemsetAsync node.

#define C 16
#define THREADS 256

struct Acc {
    float sum[C];
    float cnt[C];
    unsigned int counter;
};
__device__ Acc g_acc;

__global__ void __launch_bounds__(THREADS)
fused_kernel(const float4* __restrict__ in, float4* __restrict__ out,
             long long n4, long long chunk) {
    __shared__ float s_sum[C];
    __shared__ float s_cnt[C];
    __shared__ float s_mean[C];

    const int t = threadIdx.x;
    if (t < C) { s_sum[t] = 0.0f; s_cnt[t] = 0.0f; }
    __syncthreads();

    const long long base = (long long)blockIdx.x * chunk;
    const long long end  = (base + chunk < n4) ? (base + chunk) : n4;

    // Fixed column-group per thread: (base + t + k*256) & 3 == (base + t) & 3
    const int cg = (int)((base + t) & 3);

    float ls0 = 0.f, ls1 = 0.f, ls2 = 0.f, ls3 = 0.f;
    float lc0 = 0.f, lc1 = 0.f, lc2 = 0.f, lc3 = 0.f;

    // ---------- phase 1: reduce own tile ----------
    const long long start = base + t;
    #pragma unroll 4
    for (long long i = start; i < end; i += THREADS) {
        float4 v = in[i];
        if (v.x == v.x) { ls0 += v.x; lc0 += 1.f; }
        if (v.y == v.y) { ls1 += v.y; lc1 += 1.f; }
        if (v.z == v.z) { ls2 += v.z; lc2 += 1.f; }
        if (v.w == v.w) { ls3 += v.w; lc3 += 1.f; }
    }

    const int cbase = cg * 4;
    atomicAdd(&s_sum[cbase + 0], ls0);
    atomicAdd(&s_sum[cbase + 1], ls1);
    atomicAdd(&s_sum[cbase + 2], ls2);
    atomicAdd(&s_sum[cbase + 3], ls3);
    atomicAdd(&s_cnt[cbase + 0], lc0);
    atomicAdd(&s_cnt[cbase + 1], lc1);
    atomicAdd(&s_cnt[cbase + 2], lc2);
    atomicAdd(&s_cnt[cbase + 3], lc3);
    __syncthreads();

    if (t < C) {
        atomicAdd(&g_acc.sum[t], s_sum[t]);
        atomicAdd(&g_acc.cnt[t], s_cnt[t]);
        __threadfence();   // publish this block's contribution
    }
    __syncthreads();

    // ---------- grid barrier ----------
    if (t == 0) {
        atomicAdd(&g_acc.counter, 1u);
        volatile unsigned int* ctr = &g_acc.counter;
        while (*ctr < gridDim.x) {
            __nanosleep(64);
        }
        __threadfence();   // acquire: see all blocks' sums
    }
    __syncthreads();

    if (t < C) {
        s_mean[t] = g_acc.sum[t] / fmaxf(g_acc.cnt[t], 1.0f);
    }
    __syncthreads();

    const float m0 = s_mean[cbase + 0];
    const float m1 = s_mean[cbase + 1];
    const float m2 = s_mean[cbase + 2];
    const float m3 = s_mean[cbase + 3];

    // ---------- phase 2: reverse-order fill (L2-hot data first) ----------
    if (start < end) {
        long long K = (end - start + THREADS - 1) / THREADS;  // iterations
        #pragma unroll 4
        for (long long k = K - 1; k >= 0; k--) {
            long long i = start + k * THREADS;
            float4 v = in[i];
            if (!(v.x == v.x)) v.x = m0;
            if (!(v.y == v.y)) v.y = m1;
            if (!(v.z == v.z)) v.z = m2;
            if (!(v.w == v.w)) v.w = m3;
            out[i] = v;
        }
    }
}

extern "C" void kernel_launch(void* const* d_in, const int* in_sizes, int n_in,
                              void* d_out, int out_size) {
    const float4* in  = (const float4*)d_in[0];
    float4* out       = (float4*)d_out;
    long long n  = (long long)in_sizes[0];
    long long n4 = n / 4;

    static int grid = 0;
    static void* acc_ptr = nullptr;
    if (grid == 0) {
        int sm_count = 0;
        cudaDeviceGetAttribute(&sm_count, cudaDevAttrMultiProcessorCount, 0);
        int blocks_per_sm = 0;
        cudaOccupancyMaxActiveBlocksPerMultiprocessor(
            &blocks_per_sm, fused_kernel, THREADS, 0);
        if (blocks_per_sm < 1) blocks_per_sm = 1;
        grid = sm_count * blocks_per_sm;
        cudaGetSymbolAddress(&acc_ptr, g_acc);
    }

    long long chunk = (n4 + grid - 1) / grid;

    cudaMemsetAsync(acc_ptr, 0, sizeof(Acc));
    fused_kernel<<<grid, THREADS>>>(in, out, n4, chunk);
}